// round 14
// baseline (speedup 1.0000x reference)
#include <cuda_runtime.h>
#include <cstdint>

// x (2,4,128,128,128) f32, y (2,1,128,128,128) int32 -> scalar f32
#define SPB    (1u << 21)       // 128^3 voxels per batch
#define NTOT   (1u << 22)       // 2 * 128^3
#define NWORDS (NTOT / 32)      // packed 32-voxel words: 131072
#define NB     592u             // persistent blocks (4/SM x 148, fits 152-SM GB300)
#define NTILES (NTOT / 1024)    // 4096 tiles of 1024 voxels
#define MAXK   7                // max tiles per block: ceil(4096/592)

// Bit planes, interleaved: .x = A (P==1), .y = B (P in {0,3})
// crit = (rA & dil3D(B)) | (rB & dil3D(A))
__device__ uint2 g_rAB[NWORDS];     // raw planes
__device__ uint2 g_dAB[NWORDS];     // x-dilated planes
__device__ unsigned g_count = 0;    // barrier arrivals
__device__ unsigned g_gen   = 0;    // barrier generation (monotonic across replays)

__global__ void __launch_bounds__(256, 4)
fused(const float* __restrict__ x, const int* __restrict__ y,
      float* __restrict__ out) {
    __shared__ float         ce_s[MAXK * 1024];   // 28 KB: CE stays on-chip
    __shared__ unsigned char snib[256];
    __shared__ uint32_t      critw[MAXK][32];
    __shared__ float         ws[8];

    unsigned tid  = threadIdx.x, bid = blockIdx.x;
    unsigned lane = tid & 31u,   warp = tid >> 5;
    if (bid == 0 && tid == 0) out[0] = 0.0f;

    // ------------------------- phase 1: flags + CE -------------------------
    int k = 0;
    for (unsigned t = bid; t < NTILES; t += NB, k++) {
        unsigned i4 = t * 1024u + tid * 4u;
        unsigned b  = i4 >> 21;
        unsigned v  = i4 & (SPB - 1);
        const float* xb = x + (size_t)b * 4 * SPB + v;

        float4 a0 = *(const float4*)(xb);
        float4 a1 = *(const float4*)(xb + SPB);
        float4 a2 = *(const float4*)(xb + 2 * SPB);
        float4 a3 = *(const float4*)(xb + 3 * SPB);
        int4   yy = *(const int4*)(y + i4);

        float c0[4] = {a0.x, a0.y, a0.z, a0.w};
        float c1[4] = {a1.x, a1.y, a1.z, a1.w};
        float c2[4] = {a2.x, a2.y, a2.z, a2.w};
        float c3[4] = {a3.x, a3.y, a3.z, a3.w};
        int   yv[4] = {yy.x, yy.y, yy.z, yy.w};

        unsigned nib = 0;
        float* cp = &ce_s[k * 1024 + tid * 4];
        #pragma unroll
        for (int j = 0; j < 4; j++) {
            float x0 = c0[j], x1 = c1[j], x2 = c2[j], x3 = c3[j];
            float best = x0; int p = 0;
            if (x1 > best) { best = x1; p = 1; }
            if (x2 > best) { best = x2; p = 2; }
            if (x3 > best) { best = x3; p = 3; }
            unsigned A = (p == 1) ? 1u : 0u;
            unsigned B = (p == 0 || p == 3) ? 1u : 0u;
            nib |= (A << j) | (B << (j + 4));
            float m = best;
            float lse = m + __logf(__expf(x0 - m) + __expf(x1 - m) +
                                   __expf(x2 - m) + __expf(x3 - m));
            int yi = yv[j];
            float xy = (yi == 0) ? x0 : (yi == 1) ? x1 : (yi == 2) ? x2 : x3;
            cp[j] = lse - xy;
        }

        snib[tid] = (unsigned char)nib;
        __syncthreads();

        // Warp 0: assemble 32 words, x-dilate (rows = 4 words, within warp)
        if (tid < 32) {
            unsigned w = tid;
            uint32_t wA = 0, wB = 0;
            #pragma unroll
            for (int j = 0; j < 8; j++) {
                unsigned n = snib[w * 8 + j];
                wA |= (n & 0xFu) << (4 * j);
                wB |= (n >> 4)   << (4 * j);
            }
            uint32_t pA  = __shfl_up_sync(0xFFFFFFFFu, wA, 1);
            uint32_t nAx = __shfl_down_sync(0xFFFFFFFFu, wA, 1);
            uint32_t pB  = __shfl_up_sync(0xFFFFFFFFu, wB, 1);
            uint32_t nBx = __shfl_down_sync(0xFFFFFFFFu, wB, 1);
            if ((w & 3u) == 0) { pA = 0; pB = 0; }
            if ((w & 3u) == 3) { nAx = 0; nBx = 0; }
            uint32_t dA = wA | (wA << 1) | (pA >> 31) | (wA >> 1) | (nAx << 31);
            uint32_t dB = wB | (wB << 1) | (pB >> 31) | (wB >> 1) | (nBx << 31);

            unsigned gw = t * 32u + w;
            g_rAB[gw] = make_uint2(wA, wB);
            g_dAB[gw] = make_uint2(dA, dB);
        }
        __syncthreads();   // snib reused next tile
    }
    int kmax = k;

    // --------------------- device-wide software barrier --------------------
    __threadfence();       // publish this block's plane stores (all threads)
    __syncthreads();
    if (tid == 0) {
        unsigned gen = *((volatile unsigned*)&g_gen);
        __threadfence();
        if (atomicAdd(&g_count, 1) == NB - 1) {   // last arriver
            g_count = 0;
            __threadfence();
            atomicAdd(&g_gen, 1);
        } else {
            while (*((volatile unsigned*)&g_gen) == gen) __nanosleep(32);
        }
        __threadfence();
    }
    __syncthreads();
    // Safe: this block never read g_*AB before the barrier, so L1 holds no
    // stale copies; post-barrier LDGs observe L2-coherent data.

    // ------------------ phase 2a: crit words (1 warp/tile) -----------------
    if ((int)warp < kmax) {
        unsigned t  = bid + warp * NB;
        unsigned gw = t * 32u + lane;
        unsigned yr = (gw >> 2) & 127u;
        unsigned z  = (gw >> 9) & 127u;

        uint32_t nA = 0, nBv = 0;
        #pragma unroll
        for (int dz = -1; dz <= 1; dz++) {
            if ((dz == -1 && z == 0) || (dz == 1 && z == 127)) continue;
            #pragma unroll
            for (int dy = -1; dy <= 1; dy++) {
                if ((dy == -1 && yr == 0) || (dy == 1 && yr == 127)) continue;
                uint2 u = g_dAB[(int)gw + dz * 512 + dy * 4];
                nA |= u.x; nBv |= u.y;
            }
        }
        uint2 r = g_rAB[gw];
        critw[warp][lane] = (r.x & nBv) | (r.y & nA);
    }
    __syncthreads();

    // ------------------- phase 2b: masked CE sum from smem -----------------
    float s = 0.0f;
    for (int kk = 0; kk < kmax; kk++) {
        uint32_t cr = critw[kk][tid >> 3];
        unsigned sh = (tid & 7u) * 4u;
        float4 c4 = *(const float4*)&ce_s[kk * 1024 + tid * 4];
        if (cr & (1u << sh)) s += c4.x;
        if (cr & (2u << sh)) s += c4.y;
        if (cr & (4u << sh)) s += c4.z;
        if (cr & (8u << sh)) s += c4.w;
    }

    // block reduce + atomic
    #pragma unroll
    for (int o = 16; o; o >>= 1) s += __shfl_down_sync(0xFFFFFFFFu, s, o);
    if (lane == 0) ws[warp] = s;
    __syncthreads();
    if (warp == 0) {
        s = (lane < 8) ? ws[lane] : 0.0f;
        #pragma unroll
        for (int o = 4; o; o >>= 1) s += __shfl_down_sync(0xFFFFFFFFu, s, o);
        if (lane == 0) atomicAdd(out, 0.5f * s);   // mean over batch of 2
    }
}

// ---------------------------------------------------------------------------
extern "C" void kernel_launch(void* const* d_in, const int* in_sizes, int n_in,
                              void* d_out, int out_size) {
    const float* x = (const float*)d_in[0];
    const int*   y = (const int*)d_in[1];
    float* out = (float*)d_out;
    fused<<<NB, 256>>>(x, y, out);
}

// round 15
// speedup vs baseline: 1.0015x; 1.0015x over previous
#include <cuda_runtime.h>
#include <cstdint>

// x (2,4,128,128,128) f32, y (2,1,128,128,128) int32 -> scalar f32
#define SPB    (1u << 21)       // 128^3 voxels per batch
#define NTOT   (1u << 22)       // 2 * 128^3
#define NWORDS (NTOT / 32)      // packed 32-voxel words: 131072
#define NB     592u             // persistent blocks (4/SM x 148, fits 152-SM GB300)
#define NTILES (NTOT / 1024)    // 4096 tiles of 1024 voxels
#define MAXK   7                // max tiles per block: ceil(4096/592)

// Bit planes, interleaved: .x = A (P==1), .y = B (P in {0,3})
// crit = (rA & dil3D(B)) | (rB & dil3D(A))
__device__ uint2 g_rAB[NWORDS];     // raw planes
__device__ uint2 g_dAB[NWORDS];     // x-dilated planes
__device__ unsigned g_count = 0;    // barrier arrivals
__device__ unsigned g_gen   = 0;    // barrier generation (monotonic across replays)

__global__ void __launch_bounds__(256, 4)
fused(const float* __restrict__ x, const int* __restrict__ y,
      float* __restrict__ out) {
    __shared__ float         ce_s[MAXK * 1024];   // 28 KB: CE stays on-chip
    __shared__ unsigned char snib[256];
    __shared__ uint32_t      critw[MAXK][32];
    __shared__ float         ws[8];

    unsigned tid  = threadIdx.x, bid = blockIdx.x;
    unsigned lane = tid & 31u,   warp = tid >> 5;
    if (bid == 0 && tid == 0) out[0] = 0.0f;

    // ------------------------- phase 1: flags + CE -------------------------
    int k = 0;
    for (unsigned t = bid; t < NTILES; t += NB, k++) {
        unsigned i4 = t * 1024u + tid * 4u;
        unsigned b  = i4 >> 21;
        unsigned v  = i4 & (SPB - 1);
        const float* xb = x + (size_t)b * 4 * SPB + v;

        float4 a0 = *(const float4*)(xb);
        float4 a1 = *(const float4*)(xb + SPB);
        float4 a2 = *(const float4*)(xb + 2 * SPB);
        float4 a3 = *(const float4*)(xb + 3 * SPB);
        int4   yy = *(const int4*)(y + i4);

        float c0[4] = {a0.x, a0.y, a0.z, a0.w};
        float c1[4] = {a1.x, a1.y, a1.z, a1.w};
        float c2[4] = {a2.x, a2.y, a2.z, a2.w};
        float c3[4] = {a3.x, a3.y, a3.z, a3.w};
        int   yv[4] = {yy.x, yy.y, yy.z, yy.w};

        unsigned nib = 0;
        float* cp = &ce_s[k * 1024 + tid * 4];
        #pragma unroll
        for (int j = 0; j < 4; j++) {
            float x0 = c0[j], x1 = c1[j], x2 = c2[j], x3 = c3[j];
            float best = x0; int p = 0;
            if (x1 > best) { best = x1; p = 1; }
            if (x2 > best) { best = x2; p = 2; }
            if (x3 > best) { best = x3; p = 3; }
            unsigned A = (p == 1) ? 1u : 0u;
            unsigned B = (p == 0 || p == 3) ? 1u : 0u;
            nib |= (A << j) | (B << (j + 4));
            float m = best;
            float lse = m + __logf(__expf(x0 - m) + __expf(x1 - m) +
                                   __expf(x2 - m) + __expf(x3 - m));
            int yi = yv[j];
            float xy = (yi == 0) ? x0 : (yi == 1) ? x1 : (yi == 2) ? x2 : x3;
            cp[j] = lse - xy;
        }

        snib[tid] = (unsigned char)nib;
        __syncthreads();

        // Warp 0: assemble 32 words, x-dilate (rows = 4 words, within warp)
        if (tid < 32) {
            unsigned w = tid;
            uint32_t wA = 0, wB = 0;
            #pragma unroll
            for (int j = 0; j < 8; j++) {
                unsigned n = snib[w * 8 + j];
                wA |= (n & 0xFu) << (4 * j);
                wB |= (n >> 4)   << (4 * j);
            }
            uint32_t pA  = __shfl_up_sync(0xFFFFFFFFu, wA, 1);
            uint32_t nAx = __shfl_down_sync(0xFFFFFFFFu, wA, 1);
            uint32_t pB  = __shfl_up_sync(0xFFFFFFFFu, wB, 1);
            uint32_t nBx = __shfl_down_sync(0xFFFFFFFFu, wB, 1);
            if ((w & 3u) == 0) { pA = 0; pB = 0; }
            if ((w & 3u) == 3) { nAx = 0; nBx = 0; }
            uint32_t dA = wA | (wA << 1) | (pA >> 31) | (wA >> 1) | (nAx << 31);
            uint32_t dB = wB | (wB << 1) | (pB >> 31) | (wB >> 1) | (nBx << 31);

            unsigned gw = t * 32u + w;
            g_rAB[gw] = make_uint2(wA, wB);
            g_dAB[gw] = make_uint2(dA, dB);
        }
        __syncthreads();   // snib reused next tile
    }
    int kmax = k;

    // --------------------- device-wide software barrier --------------------
    __threadfence();       // publish this block's plane stores (all threads)
    __syncthreads();
    if (tid == 0) {
        unsigned gen = *((volatile unsigned*)&g_gen);
        __threadfence();
        if (atomicAdd(&g_count, 1) == NB - 1) {   // last arriver
            g_count = 0;
            __threadfence();
            atomicAdd(&g_gen, 1);
        } else {
            while (*((volatile unsigned*)&g_gen) == gen) __nanosleep(32);
        }
        __threadfence();
    }
    __syncthreads();
    // Safe: this block never read g_*AB before the barrier, so L1 holds no
    // stale copies; post-barrier LDGs observe L2-coherent data.

    // ------------------ phase 2a: crit words (1 warp/tile) -----------------
    if ((int)warp < kmax) {
        unsigned t  = bid + warp * NB;
        unsigned gw = t * 32u + lane;
        unsigned yr = (gw >> 2) & 127u;
        unsigned z  = (gw >> 9) & 127u;

        uint32_t nA = 0, nBv = 0;
        #pragma unroll
        for (int dz = -1; dz <= 1; dz++) {
            if ((dz == -1 && z == 0) || (dz == 1 && z == 127)) continue;
            #pragma unroll
            for (int dy = -1; dy <= 1; dy++) {
                if ((dy == -1 && yr == 0) || (dy == 1 && yr == 127)) continue;
                uint2 u = g_dAB[(int)gw + dz * 512 + dy * 4];
                nA |= u.x; nBv |= u.y;
            }
        }
        uint2 r = g_rAB[gw];
        critw[warp][lane] = (r.x & nBv) | (r.y & nA);
    }
    __syncthreads();

    // ------------------- phase 2b: masked CE sum from smem -----------------
    float s = 0.0f;
    for (int kk = 0; kk < kmax; kk++) {
        uint32_t cr = critw[kk][tid >> 3];
        unsigned sh = (tid & 7u) * 4u;
        float4 c4 = *(const float4*)&ce_s[kk * 1024 + tid * 4];
        if (cr & (1u << sh)) s += c4.x;
        if (cr & (2u << sh)) s += c4.y;
        if (cr & (4u << sh)) s += c4.z;
        if (cr & (8u << sh)) s += c4.w;
    }

    // block reduce + atomic
    #pragma unroll
    for (int o = 16; o; o >>= 1) s += __shfl_down_sync(0xFFFFFFFFu, s, o);
    if (lane == 0) ws[warp] = s;
    __syncthreads();
    if (warp == 0) {
        s = (lane < 8) ? ws[lane] : 0.0f;
        #pragma unroll
        for (int o = 4; o; o >>= 1) s += __shfl_down_sync(0xFFFFFFFFu, s, o);
        if (lane == 0) atomicAdd(out, 0.5f * s);   // mean over batch of 2
    }
}

// ---------------------------------------------------------------------------
extern "C" void kernel_launch(void* const* d_in, const int* in_sizes, int n_in,
                              void* d_out, int out_size) {
    const float* x = (const float*)d_in[0];
    const int*   y = (const int*)d_in[1];
    float* out = (float*)d_out;
    fused<<<NB, 256>>>(x, y, out);
}